// round 10
// baseline (speedup 1.0000x reference)
#include <cuda_runtime.h>

// PlasticSynapse: out = clip(baseline*a + w*(1-a) + R*|kappa|*(post*pre + s*noise), 0, 1)
// Shapes: w,noise,out: [B=64, OUT=1024, IN=1024]; baseline,kappa: [OUT,IN];
//         R: [B]; pre: [B,IN]; post: [B,OUT].
// HBM-bound elementwise: 768 MiB compulsory traffic. R9: 115.1us @ 87.4% DRAM.
// R10: ITEMS=4 at quarter-stride -> same (o,i4) per item, baseline/kappa reused
// in registers; 8 front-batched streamed LDG.128 per thread for deeper MLP.

#define B_   64
#define OUT_ 1024
#define IN_  1024
#define IN4_ (IN_ / 4)                 // 256 float4 per row
#define TOTAL4 ((B_ * OUT_ * IN_) / 4) // 16,777,216 float4
#define ITEMS 4
#define QSTRIDE (TOTAL4 / ITEMS)       // 4,194,304 -> b advances by 16 per item
#define BSTEP (B_ / ITEMS)             // 16

#define ALPHA_W   0.01f
#define ONE_M_A   0.99f
#define SIGMA_W   0.14142135623730953f
#define WBOUND    1.0f

__device__ __forceinline__ float4 psyn_elem(float4 w4, float4 n4,
                                            float4 bl, float4 kp,
                                            float4 pr, float rp, float p)
{
    float4 res;
    {
        float plas = rp * fabsf(kp.x) * fmaf(SIGMA_W, n4.x, p * pr.x);
        float v = fmaf(bl.x, ALPHA_W, fmaf(w4.x, ONE_M_A, plas));
        res.x = fminf(fmaxf(v, 0.0f), WBOUND);
    }
    {
        float plas = rp * fabsf(kp.y) * fmaf(SIGMA_W, n4.y, p * pr.y);
        float v = fmaf(bl.y, ALPHA_W, fmaf(w4.y, ONE_M_A, plas));
        res.y = fminf(fmaxf(v, 0.0f), WBOUND);
    }
    {
        float plas = rp * fabsf(kp.z) * fmaf(SIGMA_W, n4.z, p * pr.z);
        float v = fmaf(bl.z, ALPHA_W, fmaf(w4.z, ONE_M_A, plas));
        res.z = fminf(fmaxf(v, 0.0f), WBOUND);
    }
    {
        float plas = rp * fabsf(kp.w) * fmaf(SIGMA_W, n4.w, p * pr.w);
        float v = fmaf(bl.w, ALPHA_W, fmaf(w4.w, ONE_M_A, plas));
        res.w = fminf(fmaxf(v, 0.0f), WBOUND);
    }
    return res;
}

__global__ __launch_bounds__(256)
void plastic_synapse_kernel(const float4* __restrict__ w,
                            const float4* __restrict__ baseline,
                            const float*  __restrict__ R,
                            const float4* __restrict__ pre,
                            const float*  __restrict__ post,
                            const float4* __restrict__ kappa,
                            const float4* __restrict__ noise,
                            float4*       __restrict__ out)
{
    const int idx = blockIdx.x * blockDim.x + threadIdx.x;   // float4 index, item 0
    // idx = ((b * OUT_) + o) * IN4_ + i4 ; all powers of two.
    const int i4 = idx & (IN4_ - 1);
    const int o  = (idx >> 8) & (OUT_ - 1);
    const int b  = idx >> 18;            // 0..15 for item 0

    // --- Front-batched streamed loads: 8 independent LDG.128 (evict-first) ---
    float4 w0 = __ldcs(&w[idx]);
    float4 w1 = __ldcs(&w[idx +     QSTRIDE]);
    float4 w2 = __ldcs(&w[idx + 2 * QSTRIDE]);
    float4 w3 = __ldcs(&w[idx + 3 * QSTRIDE]);
    float4 n0 = __ldcs(&noise[idx]);
    float4 n1 = __ldcs(&noise[idx +     QSTRIDE]);
    float4 n2 = __ldcs(&noise[idx + 2 * QSTRIDE]);
    float4 n3 = __ldcs(&noise[idx + 3 * QSTRIDE]);

    // --- Reused operands: same (o, i4) for all 4 items -> load once ---
    const int oi = o * IN4_ + i4;
    const float4 bl = __ldg(&baseline[oi]);
    const float4 kp = __ldg(&kappa[oi]);

    const float4 pr0 = __ldg(&pre[(b             ) * IN4_ + i4]);
    const float4 pr1 = __ldg(&pre[(b +     BSTEP) * IN4_ + i4]);
    const float4 pr2 = __ldg(&pre[(b + 2 * BSTEP) * IN4_ + i4]);
    const float4 pr3 = __ldg(&pre[(b + 3 * BSTEP) * IN4_ + i4]);

    const float r0 = __ldg(&R[b]);
    const float r1 = __ldg(&R[b +     BSTEP]);
    const float r2 = __ldg(&R[b + 2 * BSTEP]);
    const float r3 = __ldg(&R[b + 3 * BSTEP]);

    const float p0 = __ldg(&post[(b             ) * OUT_ + o]);
    const float p1 = __ldg(&post[(b +     BSTEP) * OUT_ + o]);
    const float p2 = __ldg(&post[(b + 2 * BSTEP) * OUT_ + o]);
    const float p3 = __ldg(&post[(b + 3 * BSTEP) * OUT_ + o]);

    __stcs(&out[idx             ], psyn_elem(w0, n0, bl, kp, pr0, r0, p0));
    __stcs(&out[idx +     QSTRIDE], psyn_elem(w1, n1, bl, kp, pr1, r1, p1));
    __stcs(&out[idx + 2 * QSTRIDE], psyn_elem(w2, n2, bl, kp, pr2, r2, p2));
    __stcs(&out[idx + 3 * QSTRIDE], psyn_elem(w3, n3, bl, kp, pr3, r3, p3));
}

extern "C" void kernel_launch(void* const* d_in, const int* in_sizes, int n_in,
                              void* d_out, int out_size)
{
    // metadata order: w, baseline, R, pre, post, kappa, noise
    const float4* w        = (const float4*)d_in[0];
    const float4* baseline = (const float4*)d_in[1];
    const float*  R        = (const float*) d_in[2];
    const float4* pre      = (const float4*)d_in[3];
    const float*  post     = (const float*) d_in[4];
    const float4* kappa    = (const float4*)d_in[5];
    const float4* noise    = (const float4*)d_in[6];
    float4*       out      = (float4*)d_out;

    const int threads = 256;
    const int blocks  = QSTRIDE / threads;   // 16,384 blocks, each thread does 4 items

    plastic_synapse_kernel<<<blocks, threads>>>(w, baseline, R, pre, post,
                                                kappa, noise, out);
}

// round 11
// speedup vs baseline: 1.0693x; 1.0693x over previous
#include <cuda_runtime.h>

// PlasticSynapse: out = clip(baseline*a + w*(1-a) + R*|kappa|*(post*pre + s*noise), 0, 1)
// Shapes: w,noise,out: [B=64, OUT=1024, IN=1024]; baseline,kappa: [OUT,IN];
//         R: [B]; pre: [B,IN]; post: [B,OUT].
// HBM-bound elementwise: 768 MiB compulsory traffic.
// R9 (1 item/thread, 256 thr): 115.1us @ 87.4% DRAM, regs=32, occ=81%.
// R10 (4 items/thread): 122.9us — occupancy loss (regs 44, occ 54%) beat MLP gain. Reverted.
// R11: R9 structure + 128-thread blocks (finer wave grain) + __saturatef clamp.

#define B_   64
#define OUT_ 1024
#define IN_  1024
#define IN4_ (IN_ / 4)          // 256 float4 per row
#define TOTAL4 ((B_ * OUT_ * IN_) / 4)
#define ALPHA_W   0.01f
#define ONE_M_A   0.99f
#define SIGMA_W   0.14142135623730953f

__global__ __launch_bounds__(128)
void plastic_synapse_kernel(const float4* __restrict__ w,
                            const float4* __restrict__ baseline,
                            const float*  __restrict__ R,
                            const float4* __restrict__ pre,
                            const float*  __restrict__ post,
                            const float4* __restrict__ kappa,
                            const float4* __restrict__ noise,
                            float4*       __restrict__ out)
{
    const int idx = blockIdx.x * blockDim.x + threadIdx.x;   // float4 index
    // idx = ((b * OUT_) + o) * IN4_ + i4 ; all powers of two.
    const int i4 = idx & (IN4_ - 1);
    const int o  = (idx >> 8) & (OUT_ - 1);
    const int b  = idx >> 18;

    // Streamed (read-once) operands: evict-first, front-batched.
    const float4 w4 = __ldcs(&w[idx]);
    const float4 n4 = __ldcs(&noise[idx]);

    // Reused operands: L2-resident (8 MiB total), default caching.
    const int oi = o * IN4_ + i4;
    const float4 bl = __ldg(&baseline[oi]);
    const float4 kp = __ldg(&kappa[oi]);
    const float4 pr = __ldg(&pre[b * IN4_ + i4]);
    const float  r  = __ldg(&R[b]);
    const float  p  = __ldg(&post[b * OUT_ + o]);

    float4 res;
    {
        float plas = r * fabsf(kp.x) * fmaf(SIGMA_W, n4.x, p * pr.x);
        res.x = __saturatef(fmaf(bl.x, ALPHA_W, fmaf(w4.x, ONE_M_A, plas)));
    }
    {
        float plas = r * fabsf(kp.y) * fmaf(SIGMA_W, n4.y, p * pr.y);
        res.y = __saturatef(fmaf(bl.y, ALPHA_W, fmaf(w4.y, ONE_M_A, plas)));
    }
    {
        float plas = r * fabsf(kp.z) * fmaf(SIGMA_W, n4.z, p * pr.z);
        res.z = __saturatef(fmaf(bl.z, ALPHA_W, fmaf(w4.z, ONE_M_A, plas)));
    }
    {
        float plas = r * fabsf(kp.w) * fmaf(SIGMA_W, n4.w, p * pr.w);
        res.w = __saturatef(fmaf(bl.w, ALPHA_W, fmaf(w4.w, ONE_M_A, plas)));
    }

    __stcs(&out[idx], res);
}

extern "C" void kernel_launch(void* const* d_in, const int* in_sizes, int n_in,
                              void* d_out, int out_size)
{
    // metadata order: w, baseline, R, pre, post, kappa, noise
    const float4* w        = (const float4*)d_in[0];
    const float4* baseline = (const float4*)d_in[1];
    const float*  R        = (const float*) d_in[2];
    const float4* pre      = (const float4*)d_in[3];
    const float*  post     = (const float*) d_in[4];
    const float4* kappa    = (const float4*)d_in[5];
    const float4* noise    = (const float4*)d_in[6];
    float4*       out      = (float4*)d_out;

    const int threads = 128;
    const int blocks  = TOTAL4 / threads;   // 131,072 blocks

    plastic_synapse_kernel<<<blocks, threads>>>(w, baseline, R, pre, post,
                                                kappa, noise, out);
}